// round 6
// baseline (speedup 1.0000x reference)
#include <cuda_runtime.h>
#include <math.h>

#define NPROB (64 * 2048)
#define TPB 128
#define MELEMS 169
#define STAGE_FLOATS (TPB * MELEMS)      /* 21632 floats */
#define SMEM_BYTES (STAGE_FLOATS * 4)    /* 86528 bytes  */

/* upper-triangle index for 13x13 symmetric, i<=j */
#define IDXU(i, j) ((i) * 13 - ((i) * ((i) - 1)) / 2 + (j) - (i))
/* symmetric access */
#define MM(i, j) (((i) <= (j)) ? m[IDXU(i, j)] : m[IDXU(j, i)])
/* upper-triangle index for 6x6 symmetric Omega, i<=j */
#define QQ(i, j) Qm[(i) * 6 - ((i) * ((i) - 1)) / 2 + (j) - (i)]
/* lower-triangle index for 6x6 Cholesky factor, k<=i */
#define LL(i, k) Lf[(i) * ((i) + 1) / 2 + (k)]

/* dot(P_col_k, w) given T rows (Ta,Tb,Tc,Tt) in scope */
#define DOT0 (Tc[0]*w[1] - Tb[0]*w[2] + Tc[1]*w[4] - Tb[1]*w[5] + Tc[2]*w[7] - Tb[2]*w[8])
#define DOT1 (-Tc[0]*w[0] + Ta[0]*w[2] - Tc[1]*w[3] + Ta[1]*w[5] - Tc[2]*w[6] + Ta[2]*w[8])
#define DOT2 (Tb[0]*w[0] - Ta[0]*w[1] + Tb[1]*w[3] - Ta[1]*w[4] + Tb[2]*w[6] - Ta[2]*w[7])
#define DOT3 (Ta[0]*w[10] + Ta[1]*w[11] + Ta[2]*w[12])
#define DOT4 (Tb[0]*w[10] + Tb[1]*w[11] + Tb[2]*w[12])
#define DOT5 (Tc[0]*w[10] + Tc[1]*w[11] + Tc[2]*w[12])

/* w[i] = (M * p_l)[i] builders */
#define W_COL0(i) w[i] = MM(i,1)*Tc[0] - MM(i,2)*Tb[0] + MM(i,4)*Tc[1] - MM(i,5)*Tb[1] + MM(i,7)*Tc[2] - MM(i,8)*Tb[2]
#define W_COL1(i) w[i] = -MM(i,0)*Tc[0] + MM(i,2)*Ta[0] - MM(i,3)*Tc[1] + MM(i,5)*Ta[1] - MM(i,6)*Tc[2] + MM(i,8)*Ta[2]
#define W_COL2(i) w[i] = MM(i,0)*Tb[0] - MM(i,1)*Ta[0] + MM(i,3)*Tb[1] - MM(i,4)*Ta[1] + MM(i,6)*Tb[2] - MM(i,7)*Ta[2]
#define W_COL3(i) w[i] = MM(i,10)*Ta[0] + MM(i,11)*Ta[1] + MM(i,12)*Ta[2]
#define W_COL4(i) w[i] = MM(i,10)*Tb[0] + MM(i,11)*Tb[1] + MM(i,12)*Tb[2]
#define W_COL5(i) w[i] = MM(i,10)*Tc[0] + MM(i,11)*Tc[1] + MM(i,12)*Tc[2]
#define W_COL6(i) w[i] = MM(i,0)*Ta[0] + MM(i,1)*Tb[0] + MM(i,2)*Tc[0] \
                       + MM(i,3)*Ta[1] + MM(i,4)*Tb[1] + MM(i,5)*Tc[1] \
                       + MM(i,6)*Ta[2] + MM(i,7)*Tb[2] + MM(i,8)*Tc[2] \
                       + MM(i,9) \
                       + MM(i,10)*Tt[0] + MM(i,11)*Tt[1] + MM(i,12)*Tt[2]

__global__ __launch_bounds__(TPB)
void pnp_refine_kernel(const float* __restrict__ gM,
                       const float* __restrict__ gT,
                       float* __restrict__ gOut)
{
    extern __shared__ float smem[];
    const int tid = threadIdx.x;
    const int prob0 = blockIdx.x * TPB;

    /* ---- stage this block's 128 MtM matrices into shared (coalesced float4) ---- */
    {
        const float4* src = reinterpret_cast<const float4*>(gM + (size_t)prob0 * MELEMS);
        float4* dst = reinterpret_cast<float4*>(smem);
        #pragma unroll 4
        for (int i = tid; i < STAGE_FLOATS / 4; i += TPB)
            dst[i] = src[i];
    }
    __syncthreads();

    /* ---- per-thread copy of the 91 unique symmetric elements into registers ---- */
    float m[91];
    {
        const float* sm = smem + tid * MELEMS;   /* stride 169: bank-conflict-free */
        #pragma unroll
        for (int i = 0; i < 13; i++)
            #pragma unroll
            for (int j = i; j < 13; j++)
                m[IDXU(i, j)] = sm[i * 13 + j];
    }

    /* ---- load T (rows as column-vectors: Ta=T[:,0], Tb=T[:,1], Tc=T[:,2], Tt=T[:,3]) ---- */
    float Ta[3], Tb[3], Tc[3], Tt[3], R3[4];
    {
        const float4* t4 = reinterpret_cast<const float4*>(gT + (size_t)(prob0 + tid) * 16);
        float4 r0 = t4[0], r1 = t4[1], r2 = t4[2], r3 = t4[3];
        Ta[0] = r0.x; Tb[0] = r0.y; Tc[0] = r0.z; Tt[0] = r0.w;
        Ta[1] = r1.x; Tb[1] = r1.y; Tc[1] = r1.z; Tt[1] = r1.w;
        Ta[2] = r2.x; Tb[2] = r2.y; Tc[2] = r2.z; Tt[2] = r2.w;
        R3[0] = r3.x; R3[1] = r3.y; R3[2] = r3.z; R3[3] = r3.w;
    }

    float Qm[21];   /* Omega upper triangle (Q[0:6,0:6] + diag d) */
    float qv[6];    /* Q[0:6,6] */

    #pragma unroll 1
    for (int it = 0; it < 5; ++it) {
        float w[13];

        /* ----- Q = P^T M P, exploiting P column sparsity; upper triangle only ----- */
        /* l = 0 : need w at support(p0) = {1,2,4,5,7,8} */
        W_COL0(1); W_COL0(2); W_COL0(4); W_COL0(5); W_COL0(7); W_COL0(8);
        QQ(0,0) = DOT0;
        /* l = 1 */
        W_COL1(0); W_COL1(1); W_COL1(2); W_COL1(3); W_COL1(4);
        W_COL1(5); W_COL1(6); W_COL1(7); W_COL1(8);
        QQ(0,1) = DOT0; QQ(1,1) = DOT1;
        /* l = 2 */
        W_COL2(0); W_COL2(1); W_COL2(2); W_COL2(3); W_COL2(4);
        W_COL2(5); W_COL2(6); W_COL2(7); W_COL2(8);
        QQ(0,2) = DOT0; QQ(1,2) = DOT1; QQ(2,2) = DOT2;
        /* l = 3 */
        W_COL3(0); W_COL3(1); W_COL3(2); W_COL3(3); W_COL3(4);
        W_COL3(5); W_COL3(6); W_COL3(7); W_COL3(8);
        W_COL3(10); W_COL3(11); W_COL3(12);
        QQ(0,3) = DOT0; QQ(1,3) = DOT1; QQ(2,3) = DOT2; QQ(3,3) = DOT3;
        /* l = 4 */
        W_COL4(0); W_COL4(1); W_COL4(2); W_COL4(3); W_COL4(4);
        W_COL4(5); W_COL4(6); W_COL4(7); W_COL4(8);
        W_COL4(10); W_COL4(11); W_COL4(12);
        QQ(0,4) = DOT0; QQ(1,4) = DOT1; QQ(2,4) = DOT2; QQ(3,4) = DOT3; QQ(4,4) = DOT4;
        /* l = 5 */
        W_COL5(0); W_COL5(1); W_COL5(2); W_COL5(3); W_COL5(4);
        W_COL5(5); W_COL5(6); W_COL5(7); W_COL5(8);
        W_COL5(10); W_COL5(11); W_COL5(12);
        QQ(0,5) = DOT0; QQ(1,5) = DOT1; QQ(2,5) = DOT2;
        QQ(3,5) = DOT3; QQ(4,5) = DOT4; QQ(5,5) = DOT5;
        /* l = 6 (rhs column) */
        W_COL6(0); W_COL6(1); W_COL6(2); W_COL6(3); W_COL6(4);
        W_COL6(5); W_COL6(6); W_COL6(7); W_COL6(8);
        W_COL6(10); W_COL6(11); W_COL6(12);
        qv[0] = DOT0; qv[1] = DOT1; qv[2] = DOT2;
        qv[3] = DOT3; qv[4] = DOT4; qv[5] = DOT5;

        /* ----- regularization: Omega = Q66 + diag(10,10,10,regT,regT,regT) ----- */
        float trQ  = QQ(3,3) + QQ(4,4) + QQ(5,5);
        float regT = 1e-8f * fmaxf(trQ, 1.0f);
        QQ(0,0) += 10.0f; QQ(1,1) += 10.0f; QQ(2,2) += 10.0f;
        QQ(3,3) += regT;  QQ(4,4) += regT;  QQ(5,5) += regT;

        /* reg for the inverse: 1e-5 * (1 + max(Omega)) */
        float mx = Qm[0];
        #pragma unroll
        for (int i = 1; i < 21; i++) mx = fmaxf(mx, Qm[i]);
        float rg = 1e-5f * (1.0f + mx);

        /* ----- Cholesky of A = Omega + rg*I (SPD), then solve A v = -qv ----- */
        float Lf[21];
        float Dinv[6];
        #pragma unroll
        for (int i = 0; i < 6; i++) {
            float s = QQ(i, i) + rg;
            #pragma unroll
            for (int k = 0; k < i; k++) { float lik = LL(i, k); s -= lik * lik; }
            float d  = sqrtf(s);
            float di = 1.0f / d;
            Dinv[i] = di;
            #pragma unroll
            for (int r = i + 1; r < 6; r++) {
                float s2 = QQ(i, r);                /* A(r,i), i<r */
                #pragma unroll
                for (int k = 0; k < i; k++) s2 -= LL(r, k) * LL(i, k);
                LL(r, i) = s2 * di;
            }
        }
        float y[6];
        #pragma unroll
        for (int i = 0; i < 6; i++) {
            float s = -qv[i];
            #pragma unroll
            for (int k = 0; k < i; k++) s -= LL(i, k) * y[k];
            y[i] = s * Dinv[i];
        }
        float v[6];
        #pragma unroll
        for (int ii = 5; ii >= 0; ii--) {
            float s = y[ii];
            #pragma unroll
            for (int k = ii + 1; k < 6; k++) s -= LL(k, ii) * v[k];
            v[ii] = s * Dinv[ii];
        }

        /* ----- closed-form SE(3) exponential of hat(v) ----- */
        float w0 = v[0], w1 = v[1], w2 = v[2];
        float t0 = v[3], t1 = v[4], t2 = v[5];
        float th2 = w0 * w0 + w1 * w1 + w2 * w2;
        float Ac, Bc, Cc;
        if (th2 > 0.0625f) {
            float th = sqrtf(th2);
            float s = sinf(th), c = cosf(th);
            Ac = s / th;
            Bc = (1.0f - c) / th2;
            Cc = (1.0f - Ac) / th2;
        } else {
            Ac = 1.0f - th2 * (1.0f/6.0f)  * (1.0f - th2 * (1.0f/20.0f) * (1.0f - th2 * (1.0f/42.0f)));
            Bc = 0.5f * (1.0f - th2 * (1.0f/12.0f) * (1.0f - th2 * (1.0f/30.0f) * (1.0f - th2 * (1.0f/56.0f))));
            Cc = (1.0f/6.0f) * (1.0f - th2 * (1.0f/20.0f) * (1.0f - th2 * (1.0f/42.0f) * (1.0f - th2 * (1.0f/72.0f))));
        }
        float R00 = 1.0f + Bc * (w0 * w0 - th2);
        float R01 = Bc * w0 * w1 - Ac * w2;
        float R02 = Bc * w0 * w2 + Ac * w1;
        float R10 = Bc * w0 * w1 + Ac * w2;
        float R11 = 1.0f + Bc * (w1 * w1 - th2);
        float R12 = Bc * w1 * w2 - Ac * w0;
        float R20 = Bc * w0 * w2 - Ac * w1;
        float R21 = Bc * w1 * w2 + Ac * w0;
        float R22 = 1.0f + Bc * (w2 * w2 - th2);
        float cx = w1 * t2 - w2 * t1;
        float cy = w2 * t0 - w0 * t2;
        float cz = w0 * t1 - w1 * t0;
        float wd = w0 * t0 + w1 * t1 + w2 * t2;
        float U0 = t0 + Bc * cx + Cc * (w0 * wd - th2 * t0);
        float U1 = t1 + Bc * cy + Cc * (w1 * wd - th2 * t1);
        float U2 = t2 + Bc * cz + Cc * (w2 * wd - th2 * t2);

        /* ----- T <- T * exp(hat(v)) ----- */
        #pragma unroll
        for (int i = 0; i < 3; i++) {
            float na = Ta[i] * R00 + Tb[i] * R10 + Tc[i] * R20;
            float nb = Ta[i] * R01 + Tb[i] * R11 + Tc[i] * R21;
            float nc = Ta[i] * R02 + Tb[i] * R12 + Tc[i] * R22;
            float nt = Ta[i] * U0  + Tb[i] * U1  + Tc[i] * U2 + Tt[i];
            Ta[i] = na; Tb[i] = nb; Tc[i] = nc; Tt[i] = nt;
        }
        {
            float na = R3[0] * R00 + R3[1] * R10 + R3[2] * R20;
            float nb = R3[0] * R01 + R3[1] * R11 + R3[2] * R21;
            float nc = R3[0] * R02 + R3[1] * R12 + R3[2] * R22;
            float nt = R3[0] * U0  + R3[1] * U1  + R3[2] * U2 + R3[3];
            R3[0] = na; R3[1] = nb; R3[2] = nc; R3[3] = nt;
        }
    }

    /* ---- stage results into shared (transposed, padded) for coalesced f32 output ---- */
    __syncthreads();   /* everyone done reading staged M */
    float* sOut = smem;
    const int OP = 129;   /* row pitch in floats (padded: gcd(129,32)=1, conflict-free) */

    #pragma unroll
    for (int i = 0; i < 3; i++) {
        sOut[(i * 4 + 0) * OP + tid] = Ta[i];
        sOut[(i * 4 + 1) * OP + tid] = Tb[i];
        sOut[(i * 4 + 2) * OP + tid] = Tc[i];
        sOut[(i * 4 + 3) * OP + tid] = Tt[i];
    }
    sOut[12 * OP + tid] = R3[0];
    sOut[13 * OP + tid] = R3[1];
    sOut[14 * OP + tid] = R3[2];
    sOut[15 * OP + tid] = R3[3];

    {
        float denom = Tt[2] * Tt[2] + 1e-8f;   /* Tnew[2,3]^2 + 1e-8 */
        float invd  = 1.0f / denom;
        #pragma unroll
        for (int i = 0; i < 6; i++)
            #pragma unroll
            for (int j = 0; j < 6; j++) {
                float valf = ((i <= j) ? QQ(i, j) : QQ(j, i)) * invd;
                sOut[(16 + i * 6 + j) * OP + tid] = valf;
            }
    }
    __syncthreads();

    /* ---- coalesced copy out: T at [0, NPROB*16), Omega after ---- */
    float* gTo = gOut;
    float* gOo = gOut + (size_t)NPROB * 16;
    #pragma unroll 1
    for (int idx = tid; idx < TPB * 52; idx += TPB) {
        int p = idx / 52;
        int e = idx - p * 52;
        float val = sOut[e * OP + p];
        if (e < 16) gTo[(size_t)(prob0 + p) * 16 + e] = val;
        else        gOo[(size_t)(prob0 + p) * 36 + (e - 16)] = val;
    }
}

extern "C" void kernel_launch(void* const* d_in, const int* in_sizes, int n_in,
                              void* d_out, int out_size)
{
    const float* gM = (const float*)d_in[0];   /* MTMs: [64,2048,13,13] f32 */
    const float* gT = (const float*)d_in[1];   /* Ts:   [64,2048,4,4]   f32 */
    float* out = (float*)d_out;                /* T (16/prob) then Omega (36/prob), f32 */

    cudaFuncSetAttribute(pnp_refine_kernel,
                         cudaFuncAttributeMaxDynamicSharedMemorySize, SMEM_BYTES);
    pnp_refine_kernel<<<NPROB / TPB, TPB, SMEM_BYTES>>>(gM, gT, out);
}